// round 5
// baseline (speedup 1.0000x reference)
#include <cuda_runtime.h>
#include <cstdint>

// TraitSimilarity: out = (1/465) * sum over pairs 1<=j<k<32 of
//   [ (Gt[j,k] - cs_j*cs_k/N) >= 0 ] * (1 - Gp[j,k]/max(pn_j*pn_k, 1e-8))
// Gp = y_pred^T y_pred, Gt = y_true^T y_true, cs = colsum(y_true), pn=sqrt(diag Gp)

#define NBLK 740     // 5 CTAs/SM * 148 SMs -> one clean wave
#define TPB  128     // 4 warps

// scratch: per block [Gp(1024) | Gt(1024) | colsum(32)] = 2080 floats
__device__ float g_scratch[NBLK * 2080];
__device__ float g_reduced[2080];

// ---------------- packed f32x2 helpers ----------------
__device__ __forceinline__ unsigned long long pack2(float lo, float hi) {
    unsigned long long r;
    asm("mov.b64 %0, {%1, %2};" : "=l"(r) : "f"(lo), "f"(hi));
    return r;
}
__device__ __forceinline__ void fma2(unsigned long long& d,
                                     unsigned long long a,
                                     unsigned long long b) {
    asm("fma.rn.f32x2 %0, %1, %2, %0;" : "+l"(d) : "l"(a), "l"(b));
}
__device__ __forceinline__ void add2(unsigned long long& d, unsigned long long a) {
    asm("add.rn.f32x2 %0, %0, %1;" : "+l"(d) : "l"(a));
}
__device__ __forceinline__ float2 unpack2(unsigned long long v) {
    float2 f;
    asm("mov.b64 {%0, %1}, %2;" : "=f"(f.x), "=f"(f.y) : "l"(v));
    return f;
}

// ---------------- per-row FMA block ----------------
// Lane (jb in 0..7, kb in 0..3) accumulates C[4*jb+j][8*kb+kk], j 0..3, kk 0..7;
// acc[j*4+i] = f32x2 pair (kk=2i, kk=2i+1).
template <bool COLSUM>
__device__ __forceinline__ void row_fma(float4 av, ulonglong2 qa, ulonglong2 qb,
                                        unsigned long long* __restrict__ acc,
                                        unsigned long long* __restrict__ cs) {
    unsigned long long b0 = qa.x, b1 = qa.y, b2 = qb.x, b3 = qb.y;
    unsigned long long a0 = pack2(av.x, av.x);
    unsigned long long a1 = pack2(av.y, av.y);
    unsigned long long a2 = pack2(av.z, av.z);
    unsigned long long a3 = pack2(av.w, av.w);

    fma2(acc[0],  a0, b0); fma2(acc[1],  a0, b1); fma2(acc[2],  a0, b2); fma2(acc[3],  a0, b3);
    fma2(acc[4],  a1, b0); fma2(acc[5],  a1, b1); fma2(acc[6],  a1, b2); fma2(acc[7],  a1, b3);
    fma2(acc[8],  a2, b0); fma2(acc[9],  a2, b1); fma2(acc[10], a2, b2); fma2(acc[11], a2, b3);
    fma2(acc[12], a3, b0); fma2(acc[13], a3, b1); fma2(acc[14], a3, b2); fma2(acc[15], a3, b3);

    if (COLSUM) { add2(cs[0], b0); add2(cs[1], b1); add2(cs[2], b2); add2(cs[3], b3); }
}

// ---------------- Gram over one source: batched loads (MLP=12) ----------------
template <bool COLSUM>
__device__ void gram_phase(const float* __restrict__ src, int row0, int rend,
                           int jb, int kb,
                           unsigned long long* __restrict__ acc,
                           unsigned long long* __restrict__ cs) {
    int r = row0;
    for (; r + 4 <= rend; r += 4) {
        float4 a[4]; ulonglong2 q0[4], q1[4];
#pragma unroll
        for (int u = 0; u < 4; ++u) {
            const float4* rowp = (const float4*)(src + (size_t)(r + u) * 32);
            a[u]  = rowp[jb];
            const ulonglong2* rowq = (const ulonglong2*)rowp;
            q0[u] = rowq[2 * kb];
            q1[u] = rowq[2 * kb + 1];
        }
#pragma unroll
        for (int u = 0; u < 4; ++u)
            row_fma<COLSUM>(a[u], q0[u], q1[u], acc, cs);
    }
    for (; r < rend; ++r) {
        const float4* rowp = (const float4*)(src + (size_t)r * 32);
        const ulonglong2* rowq = (const ulonglong2*)rowp;
        row_fma<COLSUM>(rowp[jb], rowq[2 * kb], rowq[2 * kb + 1], acc, cs);
    }
}

// cross-warp reduce of the 32x32 tile into scratch
__device__ void store_reduce(float (*sm)[1024], float* __restrict__ outp,
                             int w, int jb, int kb,
                             const unsigned long long* __restrict__ acc) {
#pragma unroll
    for (int j = 0; j < 4; ++j) {
        const int jj = jb * 4 + j;
#pragma unroll
        for (int i = 0; i < 4; ++i) {
            float2 f = unpack2(acc[j * 4 + i]);
            const int kk = kb * 8 + 2 * i;
            sm[w][jj * 32 + kk]     = f.x;
            sm[w][jj * 32 + kk + 1] = f.y;
        }
    }
    __syncthreads();
    for (int o = threadIdx.x; o < 1024; o += TPB)
        outp[o] = sm[0][o] + sm[1][o] + sm[2][o] + sm[3][o];
    __syncthreads();
}

__global__ void __launch_bounds__(TPB, 5)
gram_kernel(const float* __restrict__ yp, const float* __restrict__ yt, int N) {
    __shared__ float sm[4][1024];
    __shared__ float smcs[4][32];

    const int w    = threadIdx.x >> 5;
    const int lane = threadIdx.x & 31;
    const int jb   = lane >> 2;
    const int kb   = lane & 3;

    const int rpb   = (N + NBLK - 1) / NBLK;
    const int brow0 = blockIdx.x * rpb;
    const int nrows = min(rpb, N - brow0);
    const int rpw   = (nrows + 3) / 4;
    const int row0  = brow0 + w * rpw;
    const int rend  = min(brow0 + nrows, row0 + rpw);

    float* outb = &g_scratch[(size_t)blockIdx.x * 2080];

    unsigned long long acc[16];
    unsigned long long cs[4];

    // ---------- phase 1: Gp from y_pred ----------
#pragma unroll
    for (int i = 0; i < 16; ++i) acc[i] = 0ull;
    gram_phase<false>(yp, row0, rend, jb, kb, acc, cs);
    store_reduce(sm, outb, w, jb, kb, acc);

    // ---------- phase 2: Gt + colsum from y_true ----------
#pragma unroll
    for (int i = 0; i < 16; ++i) acc[i] = 0ull;
#pragma unroll
    for (int i = 0; i < 4; ++i) cs[i] = 0ull;
    gram_phase<true>(yt, row0, rend, jb, kb, acc, cs);

    if (jb == 0) {   // lane holds warp colsum for k = 8*kb .. 8*kb+7
#pragma unroll
        for (int i = 0; i < 4; ++i) {
            float2 f = unpack2(cs[i]);
            smcs[w][kb * 8 + 2 * i]     = f.x;
            smcs[w][kb * 8 + 2 * i + 1] = f.y;
        }
    }
    store_reduce(sm, outb + 1024, w, jb, kb, acc);
    if (threadIdx.x < 32) {
        const int t = threadIdx.x;
        outb[2048 + t] = smcs[0][t] + smcs[1][t] + smcs[2][t] + smcs[3][t];
    }
}

// ---------------- cross-block reduction (deterministic order) ----------------
__global__ void reduce_kernel() {
    __shared__ float sm[256];
    const int ol = threadIdx.x & 15;
    const int b0 = threadIdx.x >> 4;
    const int o  = blockIdx.x * 16 + ol;

    float s = 0.0f;
    for (int b = b0; b < NBLK; b += 16)
        s += g_scratch[(size_t)b * 2080 + o];
    sm[threadIdx.x] = s;
    __syncthreads();
#pragma unroll
    for (int d = 8; d > 0; d >>= 1) {
        if (b0 < d) sm[b0 * 16 + ol] += sm[(b0 + d) * 16 + ol];
        __syncthreads();
    }
    if (threadIdx.x < 16)
        g_reduced[blockIdx.x * 16 + threadIdx.x] = sm[threadIdx.x];
}

// ---------------- finalize: one warp ----------------
__global__ void final_kernel(float* __restrict__ out, float invN) {
    __shared__ float pn[32], csm[32];
    const int lane = threadIdx.x;
    pn[lane]  = sqrtf(g_reduced[lane * 33]);       // sqrt(Gp[j][j])
    csm[lane] = g_reduced[2048 + lane];
    __syncwarp();

    float sum = 0.0f;
    for (int idx = lane; idx < 465; idx += 32) {   // pairs 1 <= j < k < 32
        int j = 1, rem = idx;
        while (rem >= 31 - j) { rem -= 31 - j; ++j; }
        const int k = j + 1 + rem;
        const float num  = g_reduced[1024 + j * 32 + k] - csm[j] * csm[k] * invN;
        const float cosv = g_reduced[j * 32 + k] / fmaxf(pn[j] * pn[k], 1e-8f);
        if (num >= 0.0f) sum += 1.0f - cosv;
    }
#pragma unroll
    for (int d = 16; d > 0; d >>= 1)
        sum += __shfl_down_sync(0xffffffffu, sum, d);
    if (lane == 0) out[0] = sum / 465.0f;
}

extern "C" void kernel_launch(void* const* d_in, const int* in_sizes, int n_in,
                              void* d_out, int out_size) {
    const float* yp = (const float*)d_in[0];   // y_pred [N, 32]
    const float* yt = (const float*)d_in[1];   // y_true [N, 32]
    const int N = in_sizes[0] / 32;

    gram_kernel<<<NBLK, TPB>>>(yp, yt, N);
    reduce_kernel<<<130, 256>>>();
    final_kernel<<<1, 32>>>((float*)d_out, 1.0f / (float)N);
}

// round 10
// speedup vs baseline: 1.3970x; 1.3970x over previous
#include <cuda_runtime.h>
#include <cstdint>

// TraitSimilarity via warp-level mma.sync tf32 (baseline PTX, sm_80+).
// Gram products per 8-sample block: P = Phi^T Phi (cos), H = Thi^T Thi,
// L = Tlo^T Thi;  Gt = H + L + L^T (split-tf32, lo*lo dropped).
// Fragment trick: per-lane loads e[u][c] = X[s + q + 4u][g + 8c]
// (q=lane%4, g=lane/4) serve BOTH A and B fragments of m16n8k8 -> zero
// duplication, no smem, no shuffles in the hot loop.

#define NCTA   592
#define TPB    128
#define NWARPS (NCTA * 4)

__device__ float g_part[NCTA * 3104];   // per CTA: P(1024) H(1024) L(1024) cs(32)
__device__ float g_red[3104];

static __device__ __forceinline__ uint32_t f2tf(float x) {
    uint32_t r; asm("cvt.rna.tf32.f32 %0, %1;" : "=r"(r) : "f"(x));
    return r;
}
static __device__ __forceinline__ void mma8(float* d,
        uint32_t a0, uint32_t a1, uint32_t a2, uint32_t a3,
        uint32_t b0, uint32_t b1) {
    asm volatile(
        "mma.sync.aligned.m16n8k8.row.col.f32.tf32.tf32.f32 "
        "{%0,%1,%2,%3}, {%4,%5,%6,%7}, {%8,%9}, {%0,%1,%2,%3};"
        : "+f"(d[0]), "+f"(d[1]), "+f"(d[2]), "+f"(d[3])
        : "r"(a0), "r"(a1), "r"(a2), "r"(a3), "r"(b0), "r"(b1));
}
// A-tile mt (traits 16mt..16mt+15), B-tile nt (traits 8nt..8nt+7)
#define MMA_T(dst, A, mt, B, nt) \
    mma8(dst, A[2*(mt)], A[2*(mt)+1], A[4+2*(mt)], A[4+2*(mt)+1], B[(nt)], B[4+(nt)])

__global__ void __launch_bounds__(TPB, 3)
gram_mma(const float* __restrict__ yp, const float* __restrict__ yt, int nblocks) {
    __shared__ float smg[3][32][33];
    __shared__ float smcs[32];

    const int tid = threadIdx.x, wid = tid >> 5, lane = tid & 31;
    const int g = lane >> 2, q = lane & 3;
    const int W = blockIdx.x * 4 + wid;
    const int laneoff = q * 32 + g;     // float offset within 8x32 block

    // accumulators: 6 symmetric tiles for P and H, 8 full tiles for L
    float accP[6][4], accH[6][4], accL[8][4];
#pragma unroll
    for (int i = 0; i < 6; ++i)
#pragma unroll
        for (int j = 0; j < 4; ++j) { accP[i][j] = 0.f; accH[i][j] = 0.f; }
#pragma unroll
    for (int i = 0; i < 8; ++i)
#pragma unroll
        for (int j = 0; j < 4; ++j) accL[i][j] = 0.f;
    float cs[4] = {0.f, 0.f, 0.f, 0.f};

    float rp[8], rt[8], np[8], nt_[8];
    int b = W;
    if (b < nblocks) {
        const float* P = yp + (size_t)b * 256 + laneoff;
        const float* T = yt + (size_t)b * 256 + laneoff;
#pragma unroll
        for (int u = 0; u < 2; ++u)
#pragma unroll
            for (int c = 0; c < 4; ++c) {
                rp[u * 4 + c] = P[u * 128 + c * 8];
                rt[u * 4 + c] = T[u * 128 + c * 8];
            }
    }

    while (b < nblocks) {
        const int nb = b + NWARPS;
        if (nb < nblocks) {
            const float* P = yp + (size_t)nb * 256 + laneoff;
            const float* T = yt + (size_t)nb * 256 + laneoff;
#pragma unroll
            for (int u = 0; u < 2; ++u)
#pragma unroll
                for (int c = 0; c < 4; ++c) {
                    np[u * 4 + c]  = P[u * 128 + c * 8];
                    nt_[u * 4 + c] = T[u * 128 + c * 8];
                }
        }

        uint32_t ph[8], th[8], tl[8];
#pragma unroll
        for (int i = 0; i < 8; ++i) ph[i] = f2tf(rp[i]);
#pragma unroll
        for (int i = 0; i < 8; ++i) {
            th[i] = f2tf(rt[i]);
            tl[i] = f2tf(rt[i] - __uint_as_float(th[i]));
        }
#pragma unroll
        for (int c = 0; c < 4; ++c) { cs[c] += rt[c]; cs[c] += rt[4 + c]; }

        // symmetric products: tiles (0,0)(0,1)(0,2)(0,3)(1,2)(1,3)
        MMA_T(accP[0], ph, 0, ph, 0);  MMA_T(accH[0], th, 0, th, 0);
        MMA_T(accP[1], ph, 0, ph, 1);  MMA_T(accH[1], th, 0, th, 1);
        MMA_T(accP[2], ph, 0, ph, 2);  MMA_T(accH[2], th, 0, th, 2);
        MMA_T(accP[3], ph, 0, ph, 3);  MMA_T(accH[3], th, 0, th, 3);
        MMA_T(accP[4], ph, 1, ph, 2);  MMA_T(accH[4], th, 1, th, 2);
        MMA_T(accP[5], ph, 1, ph, 3);  MMA_T(accH[5], th, 1, th, 3);
        // L = Tlo^T Thi, all 8 tiles
        MMA_T(accL[0], tl, 0, th, 0);  MMA_T(accL[1], tl, 0, th, 1);
        MMA_T(accL[2], tl, 0, th, 2);  MMA_T(accL[3], tl, 0, th, 3);
        MMA_T(accL[4], tl, 1, th, 0);  MMA_T(accL[5], tl, 1, th, 1);
        MMA_T(accL[6], tl, 1, th, 2);  MMA_T(accL[7], tl, 1, th, 3);

        b = nb;
#pragma unroll
        for (int i = 0; i < 8; ++i) { rp[i] = np[i]; rt[i] = nt_[i]; }
    }

    // ---------------- epilogue ----------------
    for (int o = tid; o < 3 * 32 * 33; o += TPB) ((float*)smg)[o] = 0.f;
    if (tid < 32) smcs[tid] = 0.f;
    __syncthreads();

    // quad-reduce colsum: trait = g + 8c, owned by q==0
#pragma unroll
    for (int c = 0; c < 4; ++c) {
        cs[c] += __shfl_xor_sync(0xffffffffu, cs[c], 1);
        cs[c] += __shfl_xor_sync(0xffffffffu, cs[c], 2);
    }

    const int SYM_MT[6] = {0, 0, 0, 0, 1, 1};
    const int SYM_NT[6] = {0, 1, 2, 3, 2, 3};
    for (int r = 0; r < 4; ++r) {
        if (wid == r) {
#pragma unroll
            for (int i = 0; i < 6; ++i) {
                const int r0 = 16 * SYM_MT[i] + g, c0 = 8 * SYM_NT[i] + 2 * q;
                smg[0][r0][c0]     += accP[i][0];
                smg[0][r0][c0 + 1] += accP[i][1];
                smg[0][r0 + 8][c0]     += accP[i][2];
                smg[0][r0 + 8][c0 + 1] += accP[i][3];
                smg[1][r0][c0]     += accH[i][0];
                smg[1][r0][c0 + 1] += accH[i][1];
                smg[1][r0 + 8][c0]     += accH[i][2];
                smg[1][r0 + 8][c0 + 1] += accH[i][3];
            }
#pragma unroll
            for (int i = 0; i < 8; ++i) {
                const int r0 = 16 * (i >> 2) + g, c0 = 8 * (i & 3) + 2 * q;
                smg[2][r0][c0]     += accL[i][0];
                smg[2][r0][c0 + 1] += accL[i][1];
                smg[2][r0 + 8][c0]     += accL[i][2];
                smg[2][r0 + 8][c0 + 1] += accL[i][3];
            }
            if (q == 0)
#pragma unroll
                for (int c = 0; c < 4; ++c) smcs[g + 8 * c] += cs[c];
        }
        __syncthreads();
    }

    float* outp = g_part + (size_t)blockIdx.x * 3104;
    for (int o = tid; o < 3072; o += TPB) {
        const int p = o >> 10, rc = o & 1023;
        outp[o] = smg[p][rc >> 5][rc & 31];
    }
    if (tid < 32) outp[3072 + tid] = smcs[tid];
}

// ---------------- deterministic cross-CTA reduction ----------------
// 16 partial-lanes per output, fixed tree order.
__global__ void reduce2() {
    __shared__ float sm[128];
    const int idx = blockIdx.x * 128 + threadIdx.x;
    const int o = idx >> 4, part = idx & 15;
    float s = 0.f;
    if (o < 3104) {
#pragma unroll 4
        for (int cta = part; cta < NCTA; cta += 16)
            s += g_part[(size_t)cta * 3104 + o];
    }
    sm[threadIdx.x] = s;
    __syncthreads();
#pragma unroll
    for (int d = 8; d > 0; d >>= 1) {
        if (part < d) sm[threadIdx.x] += sm[threadIdx.x + d];
        __syncthreads();
    }
    if (part == 0 && o < 3104) g_red[o] = sm[threadIdx.x];
}

// ---------------- finalize: one warp ----------------
__global__ void final3(float* __restrict__ out, float invN) {
    __shared__ float pn[32], csm[32];
    const int lane = threadIdx.x;
    pn[lane]  = sqrtf(g_red[lane * 32 + lane]);   // sqrt(P[j][j])
    csm[lane] = g_red[3072 + lane];
    __syncwarp();

    float sum = 0.f;
    for (int idx = lane; idx < 465; idx += 32) {  // pairs 1 <= j < k < 32
        int j = 1, rem = idx;
        while (rem >= 31 - j) { rem -= 31 - j; ++j; }
        const int k = j + 1 + rem;
        const float gt = g_red[1024 + j * 32 + k]          // H[j][k]
                       + g_red[2048 + j * 32 + k]          // L[j][k]
                       + g_red[2048 + k * 32 + j];         // L[k][j]
        const float num  = gt - csm[j] * csm[k] * invN;
        const float cosv = g_red[j * 32 + k] / fmaxf(pn[j] * pn[k], 1e-8f);
        if (num >= 0.f) sum += 1.f - cosv;
    }
#pragma unroll
    for (int d = 16; d > 0; d >>= 1)
        sum += __shfl_down_sync(0xffffffffu, sum, d);
    if (lane == 0) out[0] = sum / 465.0f;
}

extern "C" void kernel_launch(void* const* d_in, const int* in_sizes, int n_in,
                              void* d_out, int out_size) {
    const float* yp = (const float*)d_in[0];   // y_pred [N, 32]
    const float* yt = (const float*)d_in[1];   // y_true [N, 32]
    const int N = in_sizes[0] / 32;
    const int nblocks = N / 8;

    gram_mma<<<NCTA, TPB>>>(yp, yt, nblocks);
    reduce2<<<(3104 * 16 + 127) / 128, 128>>>();
    final3<<<1, 32>>>((float*)d_out, 1.0f / (float)N);
}

// round 12
// speedup vs baseline: 1.4733x; 1.0546x over previous
#include <cuda_runtime.h>
#include <cstdint>

// TraitSimilarity via warp-level mma.sync tf32 (baseline PTX, sm_80+).
// Gram products per 8-sample block: P = Phi^T Phi (cos), H = Thi^T Thi,
// L = Tlo^T Thi;  Gt = H + L + L^T (split-tf32, lo*lo dropped).
// Fragment trick: per-lane loads e[u][c] = X[s + q + 4u][g + 8c]
// (q=lane%4, g=lane/4) serve BOTH A and B fragments of m16n8k8 -> zero
// duplication, no smem, no shuffles in the hot loop.

#define NCTA   592   // 4 CTAs/SM * 148 SMs -> one clean wave at 128 regs
#define TPB    128
#define NWARPS (NCTA * 4)

__device__ float g_part[NCTA * 3104];   // per CTA: P(1024) H(1024) L(1024) cs(32)
__device__ float g_red[3104];

static __device__ __forceinline__ uint32_t f2tf(float x) {
    uint32_t r; asm("cvt.rna.tf32.f32 %0, %1;" : "=r"(r) : "f"(x));
    return r;
}
static __device__ __forceinline__ void mma8(float* d,
        uint32_t a0, uint32_t a1, uint32_t a2, uint32_t a3,
        uint32_t b0, uint32_t b1) {
    asm volatile(
        "mma.sync.aligned.m16n8k8.row.col.f32.tf32.tf32.f32 "
        "{%0,%1,%2,%3}, {%4,%5,%6,%7}, {%8,%9}, {%0,%1,%2,%3};"
        : "+f"(d[0]), "+f"(d[1]), "+f"(d[2]), "+f"(d[3])
        : "r"(a0), "r"(a1), "r"(a2), "r"(a3), "r"(b0), "r"(b1));
}
// A-tile mt (traits 16mt..16mt+15), B-tile nt (traits 8nt..8nt+7)
#define MMA_T(dst, A, mt, B, nt) \
    mma8(dst, A[2*(mt)], A[2*(mt)+1], A[4+2*(mt)], A[4+2*(mt)+1], B[(nt)], B[4+(nt)])

__global__ void __launch_bounds__(TPB, 4)
gram_mma(const float* __restrict__ yp, const float* __restrict__ yt, int nblocks) {
    __shared__ float smg[3][32][33];
    __shared__ float smcs[32];

    const int tid = threadIdx.x, wid = tid >> 5, lane = tid & 31;
    const int g = lane >> 2, q = lane & 3;
    const int W = blockIdx.x * 4 + wid;
    const int laneoff = q * 32 + g;     // float offset within 8x32 block

    // accumulators: 6 symmetric tiles for P and H, 8 full tiles for L
    float accP[6][4], accH[6][4], accL[8][4];
#pragma unroll
    for (int i = 0; i < 6; ++i)
#pragma unroll
        for (int j = 0; j < 4; ++j) { accP[i][j] = 0.f; accH[i][j] = 0.f; }
#pragma unroll
    for (int i = 0; i < 8; ++i)
#pragma unroll
        for (int j = 0; j < 4; ++j) accL[i][j] = 0.f;
    float cs[4] = {0.f, 0.f, 0.f, 0.f};

    for (int b = W; b < nblocks; b += NWARPS) {
        const float* P = yp + (size_t)b * 256 + laneoff;
        const float* T = yt + (size_t)b * 256 + laneoff;
        float rp[8], rt[8];
#pragma unroll
        for (int u = 0; u < 2; ++u)
#pragma unroll
            for (int c = 0; c < 4; ++c) {
                rp[u * 4 + c] = P[u * 128 + c * 8];
                rt[u * 4 + c] = T[u * 128 + c * 8];
            }

        uint32_t ph[8], th[8], tl[8];
#pragma unroll
        for (int i = 0; i < 8; ++i) ph[i] = f2tf(rp[i]);
#pragma unroll
        for (int i = 0; i < 8; ++i) {
            th[i] = f2tf(rt[i]);
            tl[i] = f2tf(rt[i] - __uint_as_float(th[i]));
        }
#pragma unroll
        for (int c = 0; c < 4; ++c) { cs[c] += rt[c]; cs[c] += rt[4 + c]; }

        // symmetric products: tiles (0,0)(0,1)(0,2)(0,3)(1,2)(1,3)
        MMA_T(accP[0], ph, 0, ph, 0);  MMA_T(accH[0], th, 0, th, 0);
        MMA_T(accP[1], ph, 0, ph, 1);  MMA_T(accH[1], th, 0, th, 1);
        MMA_T(accP[2], ph, 0, ph, 2);  MMA_T(accH[2], th, 0, th, 2);
        MMA_T(accP[3], ph, 0, ph, 3);  MMA_T(accH[3], th, 0, th, 3);
        MMA_T(accP[4], ph, 1, ph, 2);  MMA_T(accH[4], th, 1, th, 2);
        MMA_T(accP[5], ph, 1, ph, 3);  MMA_T(accH[5], th, 1, th, 3);
        // L = Tlo^T Thi, all 8 tiles
        MMA_T(accL[0], tl, 0, th, 0);  MMA_T(accL[1], tl, 0, th, 1);
        MMA_T(accL[2], tl, 0, th, 2);  MMA_T(accL[3], tl, 0, th, 3);
        MMA_T(accL[4], tl, 1, th, 0);  MMA_T(accL[5], tl, 1, th, 1);
        MMA_T(accL[6], tl, 1, th, 2);  MMA_T(accL[7], tl, 1, th, 3);
    }

    // ---------------- epilogue ----------------
    for (int o = tid; o < 3 * 32 * 33; o += TPB) ((float*)smg)[o] = 0.f;
    if (tid < 32) smcs[tid] = 0.f;
    __syncthreads();

    // quad-reduce colsum: trait = g + 8c, owned by q==0
#pragma unroll
    for (int c = 0; c < 4; ++c) {
        cs[c] += __shfl_xor_sync(0xffffffffu, cs[c], 1);
        cs[c] += __shfl_xor_sync(0xffffffffu, cs[c], 2);
    }

    const int SYM_MT[6] = {0, 0, 0, 0, 1, 1};
    const int SYM_NT[6] = {0, 1, 2, 3, 2, 3};
    for (int r = 0; r < 4; ++r) {
        if (wid == r) {
#pragma unroll
            for (int i = 0; i < 6; ++i) {
                const int r0 = 16 * SYM_MT[i] + g, c0 = 8 * SYM_NT[i] + 2 * q;
                smg[0][r0][c0]     += accP[i][0];
                smg[0][r0][c0 + 1] += accP[i][1];
                smg[0][r0 + 8][c0]     += accP[i][2];
                smg[0][r0 + 8][c0 + 1] += accP[i][3];
                smg[1][r0][c0]     += accH[i][0];
                smg[1][r0][c0 + 1] += accH[i][1];
                smg[1][r0 + 8][c0]     += accH[i][2];
                smg[1][r0 + 8][c0 + 1] += accH[i][3];
            }
#pragma unroll
            for (int i = 0; i < 8; ++i) {
                const int r0 = 16 * (i >> 2) + g, c0 = 8 * (i & 3) + 2 * q;
                smg[2][r0][c0]     += accL[i][0];
                smg[2][r0][c0 + 1] += accL[i][1];
                smg[2][r0 + 8][c0]     += accL[i][2];
                smg[2][r0 + 8][c0 + 1] += accL[i][3];
            }
            if (q == 0)
#pragma unroll
                for (int c = 0; c < 4; ++c) smcs[g + 8 * c] += cs[c];
        }
        __syncthreads();
    }

    float* outp = g_part + (size_t)blockIdx.x * 3104;
    for (int o = tid; o < 3072; o += TPB) {
        const int p = o >> 10, rc = o & 1023;
        outp[o] = smg[p][rc >> 5][rc & 31];
    }
    if (tid < 32) outp[3072 + tid] = smcs[tid];
}

// ---------------- deterministic cross-CTA reduction (coalesced) ----------------
// thread-per-output, serial CTA loop: consecutive threads touch consecutive
// addresses each iteration; order fixed.
__global__ void reduce2() {
    const int o = blockIdx.x * 128 + threadIdx.x;
    if (o >= 3104) return;
    float s0 = 0.f, s1 = 0.f, s2 = 0.f, s3 = 0.f;
    int cta = 0;
#pragma unroll 1
    for (; cta + 4 <= NCTA; cta += 4) {
        s0 += g_part[(size_t)(cta + 0) * 3104 + o];
        s1 += g_part[(size_t)(cta + 1) * 3104 + o];
        s2 += g_part[(size_t)(cta + 2) * 3104 + o];
        s3 += g_part[(size_t)(cta + 3) * 3104 + o];
    }
    for (; cta < NCTA; ++cta) s0 += g_part[(size_t)cta * 3104 + o];
    g_red[o] = ((s0 + s1) + (s2 + s3));
}

// ---------------- finalize: one warp ----------------
__global__ void final3(float* __restrict__ out, float invN) {
    __shared__ float pn[32], csm[32];
    const int lane = threadIdx.x;
    pn[lane]  = sqrtf(g_red[lane * 32 + lane]);   // sqrt(P[j][j])
    csm[lane] = g_red[3072 + lane];
    __syncwarp();

    float sum = 0.f;
    for (int idx = lane; idx < 465; idx += 32) {  // pairs 1 <= j < k < 32
        int j = 1, rem = idx;
        while (rem >= 31 - j) { rem -= 31 - j; ++j; }
        const int k = j + 1 + rem;
        const float gt = g_red[1024 + j * 32 + k]          // H[j][k]
                       + g_red[2048 + j * 32 + k]          // L[j][k]
                       + g_red[2048 + k * 32 + j];         // L[k][j]
        const float num  = gt - csm[j] * csm[k] * invN;
        const float cosv = g_red[j * 32 + k] / fmaxf(pn[j] * pn[k], 1e-8f);
        if (num >= 0.f) sum += 1.f - cosv;
    }
#pragma unroll
    for (int d = 16; d > 0; d >>= 1)
        sum += __shfl_down_sync(0xffffffffu, sum, d);
    if (lane == 0) out[0] = sum / 465.0f;
}

extern "C" void kernel_launch(void* const* d_in, const int* in_sizes, int n_in,
                              void* d_out, int out_size) {
    const float* yp = (const float*)d_in[0];   // y_pred [N, 32]
    const float* yt = (const float*)d_in[1];   // y_true [N, 32]
    const int N = in_sizes[0] / 32;
    const int nblocks = N / 8;

    gram_mma<<<NCTA, TPB>>>(yp, yt, nblocks);
    reduce2<<<(3104 + 127) / 128, 128>>>();
    final3<<<1, 32>>>((float*)d_out, 1.0f / (float)N);
}

// round 13
// speedup vs baseline: 1.9675x; 1.3355x over previous
#include <cuda_runtime.h>
#include <cstdint>

// TraitSimilarity via warp-level mma.sync tf32 (baseline PTX, sm_80+).
// Gram products per 8-sample block: P = Phi^T Phi (cos), H = Thi^T Thi,
// L = Tlo^T Thi;  Gt = H + L + L^T (split-tf32, lo*lo dropped).
// Fragment trick: per-lane loads e[u][c] = X[s + q + 4u][g + 8c]
// (q=lane%4, g=lane/4) serve BOTH A and B fragments of m16n8k8 -> zero
// duplication, no smem, no shuffles in the hot loop.

#define NCTA   592   // 4 CTAs/SM * 148 SMs -> one clean wave at 128 regs
#define TPB    128
#define NWARPS (NCTA * 4)

__device__ float g_part[NCTA * 3104];   // per CTA: P(1024) H(1024) L(1024) cs(32)
__device__ float g_red[3104];

static __device__ __forceinline__ uint32_t f2tf(float x) {
    uint32_t r; asm("cvt.rna.tf32.f32 %0, %1;" : "=r"(r) : "f"(x));
    return r;
}
static __device__ __forceinline__ void mma8(float* d,
        uint32_t a0, uint32_t a1, uint32_t a2, uint32_t a3,
        uint32_t b0, uint32_t b1) {
    asm volatile(
        "mma.sync.aligned.m16n8k8.row.col.f32.tf32.tf32.f32 "
        "{%0,%1,%2,%3}, {%4,%5,%6,%7}, {%8,%9}, {%0,%1,%2,%3};"
        : "+f"(d[0]), "+f"(d[1]), "+f"(d[2]), "+f"(d[3])
        : "r"(a0), "r"(a1), "r"(a2), "r"(a3), "r"(b0), "r"(b1));
}
// A-tile mt (traits 16mt..16mt+15), B-tile nt (traits 8nt..8nt+7)
#define MMA_T(dst, A, mt, B, nt) \
    mma8(dst, A[2*(mt)], A[2*(mt)+1], A[4+2*(mt)], A[4+2*(mt)+1], B[(nt)], B[4+(nt)])

__global__ void __launch_bounds__(TPB, 4)
gram_mma(const float* __restrict__ yp, const float* __restrict__ yt, int nblocks) {
    __shared__ float smg[3][32][33];
    __shared__ float smcs[32];

    const int tid = threadIdx.x, wid = tid >> 5, lane = tid & 31;
    const int g = lane >> 2, q = lane & 3;
    const int W = blockIdx.x * 4 + wid;
    const int laneoff = q * 32 + g;     // float offset within 8x32 block

    // accumulators: 6 symmetric tiles for P and H, 8 full tiles for L
    float accP[6][4], accH[6][4], accL[8][4];
#pragma unroll
    for (int i = 0; i < 6; ++i)
#pragma unroll
        for (int j = 0; j < 4; ++j) { accP[i][j] = 0.f; accH[i][j] = 0.f; }
#pragma unroll
    for (int i = 0; i < 8; ++i)
#pragma unroll
        for (int j = 0; j < 4; ++j) accL[i][j] = 0.f;
    float cs[4] = {0.f, 0.f, 0.f, 0.f};

    for (int b = W; b < nblocks; b += NWARPS) {
        const float* P = yp + (size_t)b * 256 + laneoff;
        const float* T = yt + (size_t)b * 256 + laneoff;
        float rp[8], rt[8];
#pragma unroll
        for (int u = 0; u < 2; ++u)
#pragma unroll
            for (int c = 0; c < 4; ++c) {
                rp[u * 4 + c] = P[u * 128 + c * 8];
                rt[u * 4 + c] = T[u * 128 + c * 8];
            }

        uint32_t ph[8], th[8], tl[8];
#pragma unroll
        for (int i = 0; i < 8; ++i) ph[i] = f2tf(rp[i]);
#pragma unroll
        for (int i = 0; i < 8; ++i) {
            th[i] = f2tf(rt[i]);
            tl[i] = f2tf(rt[i] - __uint_as_float(th[i]));
        }
#pragma unroll
        for (int c = 0; c < 4; ++c) { cs[c] += rt[c]; cs[c] += rt[4 + c]; }

        // symmetric products: tiles (0,0)(0,1)(0,2)(0,3)(1,2)(1,3)
        MMA_T(accP[0], ph, 0, ph, 0);  MMA_T(accH[0], th, 0, th, 0);
        MMA_T(accP[1], ph, 0, ph, 1);  MMA_T(accH[1], th, 0, th, 1);
        MMA_T(accP[2], ph, 0, ph, 2);  MMA_T(accH[2], th, 0, th, 2);
        MMA_T(accP[3], ph, 0, ph, 3);  MMA_T(accH[3], th, 0, th, 3);
        MMA_T(accP[4], ph, 1, ph, 2);  MMA_T(accH[4], th, 1, th, 2);
        MMA_T(accP[5], ph, 1, ph, 3);  MMA_T(accH[5], th, 1, th, 3);
        // L = Tlo^T Thi, all 8 tiles
        MMA_T(accL[0], tl, 0, th, 0);  MMA_T(accL[1], tl, 0, th, 1);
        MMA_T(accL[2], tl, 0, th, 2);  MMA_T(accL[3], tl, 0, th, 3);
        MMA_T(accL[4], tl, 1, th, 0);  MMA_T(accL[5], tl, 1, th, 1);
        MMA_T(accL[6], tl, 1, th, 2);  MMA_T(accL[7], tl, 1, th, 3);
    }

    // ---------------- epilogue ----------------
    for (int o = tid; o < 3 * 32 * 33; o += TPB) ((float*)smg)[o] = 0.f;
    if (tid < 32) smcs[tid] = 0.f;
    __syncthreads();

    // quad-reduce colsum: trait = g + 8c, owned by q==0
#pragma unroll
    for (int c = 0; c < 4; ++c) {
        cs[c] += __shfl_xor_sync(0xffffffffu, cs[c], 1);
        cs[c] += __shfl_xor_sync(0xffffffffu, cs[c], 2);
    }

    const int SYM_MT[6] = {0, 0, 0, 0, 1, 1};
    const int SYM_NT[6] = {0, 1, 2, 3, 2, 3};
    for (int r = 0; r < 4; ++r) {
        if (wid == r) {
#pragma unroll
            for (int i = 0; i < 6; ++i) {
                const int r0 = 16 * SYM_MT[i] + g, c0 = 8 * SYM_NT[i] + 2 * q;
                smg[0][r0][c0]     += accP[i][0];
                smg[0][r0][c0 + 1] += accP[i][1];
                smg[0][r0 + 8][c0]     += accP[i][2];
                smg[0][r0 + 8][c0 + 1] += accP[i][3];
                smg[1][r0][c0]     += accH[i][0];
                smg[1][r0][c0 + 1] += accH[i][1];
                smg[1][r0 + 8][c0]     += accH[i][2];
                smg[1][r0 + 8][c0 + 1] += accH[i][3];
            }
#pragma unroll
            for (int i = 0; i < 8; ++i) {
                const int r0 = 16 * (i >> 2) + g, c0 = 8 * (i & 3) + 2 * q;
                smg[2][r0][c0]     += accL[i][0];
                smg[2][r0][c0 + 1] += accL[i][1];
                smg[2][r0 + 8][c0]     += accL[i][2];
                smg[2][r0 + 8][c0 + 1] += accL[i][3];
            }
            if (q == 0)
#pragma unroll
                for (int c = 0; c < 4; ++c) smcs[g + 8 * c] += cs[c];
        }
        __syncthreads();
    }

    float* outp = g_part + (size_t)blockIdx.x * 3104;
    for (int o = tid; o < 3072; o += TPB) {
        const int p = o >> 10, rc = o & 1023;
        outp[o] = smg[p][rc >> 5][rc & 31];
    }
    if (tid < 32) outp[3072 + tid] = smcs[tid];
}

// ---------------- deterministic cross-CTA reduction (parallel partials) ----
// 32 partial-lanes per output, fixed tree order. 3104*32 threads = 776 blocks.
__global__ void reduce2() {
    __shared__ float sm[128];
    const int idx = blockIdx.x * 128 + threadIdx.x;
    const int o = idx >> 5, part = idx & 31;
    float s = 0.f;
    if (o < 3104) {
#pragma unroll 1
        for (int cta = part; cta < NCTA; cta += 32)
            s += g_part[(size_t)cta * 3104 + o];
    }
    sm[threadIdx.x] = s;
    __syncthreads();
#pragma unroll
    for (int d = 16; d > 0; d >>= 1) {
        if (part < d) sm[threadIdx.x] += sm[threadIdx.x + d];
        __syncthreads();
    }
    if (part == 0 && o < 3104) g_red[o] = sm[threadIdx.x];
}

// ---------------- finalize: one warp ----------------
__global__ void final3(float* __restrict__ out, float invN) {
    __shared__ float pn[32], csm[32];
    const int lane = threadIdx.x;
    pn[lane]  = sqrtf(g_red[lane * 32 + lane]);   // sqrt(P[j][j])
    csm[lane] = g_red[3072 + lane];
    __syncwarp();

    float sum = 0.f;
    for (int idx = lane; idx < 465; idx += 32) {  // pairs 1 <= j < k < 32
        int j = 1, rem = idx;
        while (rem >= 31 - j) { rem -= 31 - j; ++j; }
        const int k = j + 1 + rem;
        const float gt = g_red[1024 + j * 32 + k]          // H[j][k]
                       + g_red[2048 + j * 32 + k]          // L[j][k]
                       + g_red[2048 + k * 32 + j];         // L[k][j]
        const float num  = gt - csm[j] * csm[k] * invN;
        const float cosv = g_red[j * 32 + k] / fmaxf(pn[j] * pn[k], 1e-8f);
        if (num >= 0.f) sum += 1.f - cosv;
    }
#pragma unroll
    for (int d = 16; d > 0; d >>= 1)
        sum += __shfl_down_sync(0xffffffffu, sum, d);
    if (lane == 0) out[0] = sum / 465.0f;
}

extern "C" void kernel_launch(void* const* d_in, const int* in_sizes, int n_in,
                              void* d_out, int out_size) {
    const float* yp = (const float*)d_in[0];   // y_pred [N, 32]
    const float* yt = (const float*)d_in[1];   // y_true [N, 32]
    const int N = in_sizes[0] / 32;
    const int nblocks = N / 8;

    gram_mma<<<NCTA, TPB>>>(yp, yt, nblocks);
    reduce2<<<(3104 * 32 + 127) / 128, 128>>>();
    final3<<<1, 32>>>((float*)d_out, 1.0f / (float)N);
}